// round 15
// baseline (speedup 1.0000x reference)
#include <cuda_runtime.h>
#include <cuda_bf16.h>
#include <cstdint>
#include <math.h>

#define Bx 32
#define Dd 256
#define Kk 2048
#define Nn 32768
#define HWp 1024

#define Q_ELEMS   8388608
#define FULL_OUT  8421379
#define TAU       1e-2f

// ---- device scratch (no dynamic allocations allowed) ----
__device__ __nv_bfloat16 g_BhiT[Dd * Kk];   // 1 MB [D][K] normalized hi
__device__ __nv_bfloat16 g_BloT[Dd * Kk];   // 1 MB
__device__ float g_EfT[Dd * Kk];            // 2 MB [D][K] normalized fp32 (rescue)
__device__ float g_inv[Kk];
__device__ int   g_idx[Nn];
__device__ int   g_hist[Kk];
__device__ float g_part[256];
__device__ int   g_rcnt;
__device__ int   g_rlist[Nn];
__device__ unsigned long long g_best[Nn];   // packed (sortable score | 2047-idx)

// ======================= PTX helpers (compute_80+ baseline) ================
__device__ __forceinline__ uint32_t smem_u32(const void* p) {
    uint32_t a;
    asm("{ .reg .u64 t; cvta.to.shared.u64 t, %1; cvt.u32.u64 %0, t; }" : "=r"(a) : "l"(p));
    return a;
}
__device__ __forceinline__ void ldsm_x4(uint32_t* r, uint32_t addr) {
    asm volatile("ldmatrix.sync.aligned.m8n8.x4.shared.b16 {%0,%1,%2,%3}, [%4];"
        : "=r"(r[0]), "=r"(r[1]), "=r"(r[2]), "=r"(r[3]) : "r"(addr));
}
__device__ __forceinline__ void ldsm_x4_t(uint32_t* r, uint32_t addr) {
    asm volatile("ldmatrix.sync.aligned.m8n8.x4.trans.shared.b16 {%0,%1,%2,%3}, [%4];"
        : "=r"(r[0]), "=r"(r[1]), "=r"(r[2]), "=r"(r[3]) : "r"(addr));
}
__device__ __forceinline__ void mma_bf16(float* c, const uint32_t* a, const uint32_t* b) {
    asm("mma.sync.aligned.m16n8k16.row.col.f32.bf16.bf16.f32 "
        "{%0,%1,%2,%3}, {%4,%5,%6,%7}, {%8,%9}, {%0,%1,%2,%3};"
        : "+f"(c[0]), "+f"(c[1]), "+f"(c[2]), "+f"(c[3])
        : "r"(a[0]), "r"(a[1]), "r"(a[2]), "r"(a[3]), "r"(b[0]), "r"(b[1]));
}
__device__ __forceinline__ void cp_async16(uint32_t dst, const void* src) {
    asm volatile("cp.async.cg.shared.global [%0], [%1], 16;" :: "r"(dst), "l"(src) : "memory");
}
#define CP_COMMIT() asm volatile("cp.async.commit_group;" ::: "memory")
#define CP_WAIT0()  asm volatile("cp.async.wait_group 0;" ::: "memory")

__device__ __forceinline__ uint32_t f32_sortable(float f) {
    uint32_t b = __float_as_uint(f);
    return (b & 0x80000000u) ? ~b : (b | 0x80000000u);
}

// ---------------------------------------------------------------------------
// Kernel 1: per-column inverse norms + zero histogram + reset rescue count
// ---------------------------------------------------------------------------
__global__ void k_invnorm(const float* __restrict__ E) {
    int k = blockIdx.x * blockDim.x + threadIdx.x;
    float ss = 0.f;
#pragma unroll 8
    for (int d = 0; d < Dd; ++d) { float v = E[d * Kk + k]; ss = fmaf(v, v, ss); }
    g_inv[k] = 1.0f / fmaxf(sqrtf(ss), 1e-12f);
    g_hist[k] = 0;
    if (k == 0) g_rcnt = 0;
}

// ---------------------------------------------------------------------------
// Kernel 2: codebook prep: E [D,K] -> g_EfT [D][K] fp32 normalized (coalesced),
//           g_BhiT/g_BloT [D][K] bf16 split
// ---------------------------------------------------------------------------
__global__ __launch_bounds__(256) void k_prepe(const float* __restrict__ E) {
    __shared__ float t[64][65];
    const int tid = threadIdx.x;
    const int k0 = blockIdx.x * 64, d0 = blockIdx.y * 64;
#pragma unroll
    for (int i = 0; i < 16; ++i) {
        int idx = i * 256 + tid, di = idx >> 6, ki = idx & 63;
        t[di][ki] = E[(size_t)(d0 + di) * Kk + k0 + ki] * g_inv[k0 + ki];
    }
    __syncthreads();
#pragma unroll
    for (int i = 0; i < 16; ++i) {
        int idx = i * 256 + tid, ki = idx >> 6, di = idx & 63;
        g_EfT[(size_t)(d0 + di) * Kk + k0 + ki] = t[di][ki];
    }
#pragma unroll
    for (int i = 0; i < 8; ++i) {
        int idx = i * 256 + tid;
        int di = idx >> 5;
        int ki = (idx & 31) * 2;
        float v0 = t[di][ki], v1 = t[di][ki + 1];
        __nv_bfloat16 h0 = __float2bfloat16(v0);
        __nv_bfloat16 h1 = __float2bfloat16(v1);
        float l0 = v0 - __bfloat162float(h0);
        float l1 = v1 - __bfloat162float(h1);
        size_t o = (size_t)(d0 + di) * Kk + k0 + ki;
        __nv_bfloat162 hh; hh.x = h0; hh.y = h1;
        __nv_bfloat162 ll; ll.x = __float2bfloat16(l0); ll.y = __float2bfloat16(l1);
        *reinterpret_cast<__nv_bfloat162*>(&g_BhiT[o]) = hh;
        *reinterpret_cast<__nv_bfloat162*>(&g_BloT[o]) = ll;
    }
}

// ---------------------------------------------------------------------------
// Kernel 3: warp-MMA split-2 bf16 GEMM + top-2 argmax (unchanged from R14).
// scores = x_hi · (e_hi + e_lo); dropped x_lo·e_hi absorbed by rescue.
// 67KB smem -> 3 CTAs/SM.
// ---------------------------------------------------------------------------
#define SM_B   32768
#define SM_RED 65536
#define SM_TOT 68608

__global__ __launch_bounds__(256, 3) void k_mma_argmax(const float* __restrict__ x) {
    extern __shared__ char sm[];
    const uint32_t sb = smem_u32(sm);
    const int tid = threadIdx.x;
    const int lane = tid & 31;
    const int wid = tid >> 5;
    const int wm = wid & 1, wn = wid >> 1;
    const int rbase = blockIdx.x * 64;
    const int b = rbase >> 10, hw0 = rbase & 1023;
    const int ldr = tid >> 4, ldu = tid & 15;

    // ---- build A (hi only, swizzled [row][d]) from raw x ----
    {
        float* stg = (float*)(sm + SM_B);
#pragma unroll
        for (int h = 0; h < 2; ++h) {
            __syncthreads();
#pragma unroll
            for (int i = 0; i < 8; ++i) {
                int idx = i * 256 + tid;
                int d = idx >> 4, r4 = idx & 15;
                float4 v = *(const float4*)(x + ((size_t)b * Dd + h * 128 + d) * HWp + hw0 + r4 * 4);
                *(float4*)&stg[d * 68 + r4 * 4] = v;
            }
            __syncthreads();
#pragma unroll
            for (int it = 0; it < 4; ++it) {
                int idx = it * 256 + tid;
                int r = idx & 63, u = idx >> 6;
                float f[8];
#pragma unroll
                for (int j = 0; j < 8; ++j) f[j] = stg[(u * 8 + j) * 68 + r];
                uint32_t hi[4];
#pragma unroll
                for (int q = 0; q < 4; ++q) {
                    __nv_bfloat162 hh;
                    hh.x = __float2bfloat16(f[2 * q]);
                    hh.y = __float2bfloat16(f[2 * q + 1]);
                    hi[q] = *reinterpret_cast<uint32_t*>(&hh);
                }
                int ug = h * 16 + u;
                uint32_t ad = r * 512 + ((ug ^ (r & 7)) << 4);
                *(uint4*)(sm + ad) = make_uint4(hi[0], hi[1], hi[2], hi[3]);
            }
        }
        __syncthreads();
    }

    // ---- kick off B chunk 0 (hi 8KB + lo 8KB) into stage 0 ----
#pragma unroll
    for (int j = 0; j < 2; ++j) {
        int r = j * 16 + ldr;
        size_t so = ((size_t)r * Kk) * 2 + (size_t)ldu * 16;
        uint32_t dst = sb + SM_B + r * 256 + ((ldu ^ (r & 7)) << 4);
        cp_async16(dst, (const char*)g_BhiT + so);
        cp_async16(dst + 8192, (const char*)g_BloT + so);
    }
    CP_COMMIT();
    CP_WAIT0();
    __syncthreads();

    float c[2][4][4];
#pragma unroll
    for (int mi = 0; mi < 2; ++mi)
#pragma unroll
        for (int j = 0; j < 4; ++j)
#pragma unroll
            for (int q = 0; q < 4; ++q) c[mi][j][q] = 0.f;

    float v1[4], v2[4];
    int   i1[4];
#pragma unroll
    for (int s = 0; s < 4; ++s) { v1[s] = -3.0e38f; v2[s] = -3.0e38f; i1[s] = 0; }

    int stage = 0;
    const int kk = (lane & 7) + ((lane >> 3) & 1) * 8;

    for (int cid = 0; cid < 128; ++cid) {
        const int ct = cid >> 3, kc = cid & 7;

        if (cid < 127) {
            int nct = (cid + 1) >> 3, nkc = (cid + 1) & 7;
#pragma unroll
            for (int j = 0; j < 2; ++j) {
                int r = j * 16 + ldr;
                size_t so = ((size_t)(nkc * 32 + r) * Kk + nct * 128) * 2 + (size_t)ldu * 16;
                uint32_t dst = sb + SM_B + (stage ^ 1) * 16384 + r * 256 + ((ldu ^ (r & 7)) << 4);
                cp_async16(dst, (const char*)g_BhiT + so);
                cp_async16(dst + 8192, (const char*)g_BloT + so);
            }
        }
        CP_COMMIT();

#pragma unroll
        for (int kcs = 0; kcs < 2; ++kcs) {
            uint32_t ah[2][4];
#pragma unroll
            for (int mi = 0; mi < 2; ++mi) {
                int r0 = wm * 32 + mi * 16 + (lane & 15);
                int u0 = kc * 4 + kcs * 2 + (lane >> 4);
                uint32_t aaddr = sb + r0 * 512 + ((u0 ^ (r0 & 7)) << 4);
                ldsm_x4(ah[mi], aaddr);
            }
            uint32_t bh[2][4], bl[2][4];
            const uint32_t bbase = sb + SM_B + stage * 16384 + kcs * 4096;
#pragma unroll
            for (int p = 0; p < 2; ++p) {
                int u0 = wn * 4 + p * 2 + (lane >> 4);
                uint32_t baddr = bbase + kk * 256 + ((u0 ^ (kk & 7)) << 4);
                ldsm_x4_t(bh[p], baddr);
                ldsm_x4_t(bl[p], baddr + 8192);
            }
            // ---- 16 HMMA: hi*(hi + lo) ----
#pragma unroll
            for (int mi = 0; mi < 2; ++mi)
#pragma unroll
                for (int p = 0; p < 2; ++p) {
                    mma_bf16(c[mi][2 * p],     ah[mi], &bh[p][0]);
                    mma_bf16(c[mi][2 * p + 1], ah[mi], &bh[p][2]);
                    mma_bf16(c[mi][2 * p],     ah[mi], &bl[p][0]);
                    mma_bf16(c[mi][2 * p + 1], ah[mi], &bl[p][2]);
                }
        }

        if (kc == 7) {
            const int cb = ct * 128 + wn * 32 + (lane & 3) * 2;
#pragma unroll
            for (int mi = 0; mi < 2; ++mi)
#pragma unroll
                for (int j = 0; j < 4; ++j)
#pragma unroll
                    for (int q = 0; q < 4; ++q) {
                        float v = c[mi][j][q];
                        int col = cb + j * 8 + (q & 1);
                        int slot = mi * 2 + (q >> 1);
                        if (v > v1[slot]) { v2[slot] = v1[slot]; v1[slot] = v; i1[slot] = col; }
                        else if (v > v2[slot]) { v2[slot] = v; }
                        c[mi][j][q] = 0.f;
                    }
        }

        CP_WAIT0();
        __syncthreads();
        stage ^= 1;
    }

#pragma unroll
    for (int s = 0; s < 4; ++s) {
#pragma unroll
        for (int m = 1; m <= 2; m <<= 1) {
            float ov1 = __shfl_xor_sync(0xffffffffu, v1[s], m);
            float ov2 = __shfl_xor_sync(0xffffffffu, v2[s], m);
            int   oi1 = __shfl_xor_sync(0xffffffffu, i1[s], m);
            if (ov1 > v1[s]) { v2[s] = fmaxf(v1[s], ov2); v1[s] = ov1; i1[s] = oi1; }
            else             { v2[s] = fmaxf(v2[s], ov1); }
        }
    }
    float* sv1 = (float*)(sm + SM_RED);
    float* sv2 = (float*)(sm + SM_RED + 1024);
    int*   si1 = (int*)  (sm + SM_RED + 2048);
    if ((lane & 3) == 0) {
#pragma unroll
        for (int s = 0; s < 4; ++s) {
            int row = wm * 32 + (s >> 1) * 16 + (s & 1) * 8 + (lane >> 2);
            sv1[row * 4 + wn] = v1[s];
            sv2[row * 4 + wn] = v2[s];
            si1[row * 4 + wn] = i1[s];
        }
    }
    __syncthreads();
    if (tid < 64) {
        float t1 = -3.0e38f, t2 = -3.0e38f;
        int ti = 0;
#pragma unroll
        for (int p = 0; p < 4; ++p) {
            float a1 = sv1[tid * 4 + p], a2 = sv2[tid * 4 + p];
            int ai = si1[tid * 4 + p];
            if (a1 > t1) { t2 = fmaxf(t1, a2); t1 = a1; ti = ai; }
            else         { t2 = fmaxf(t2, a1); }
        }
        g_idx[rbase + tid] = ti;
        if (t1 - t2 < TAU) {
            g_best[rbase + tid] = 0ULL;          // floor for atomicMax keys
            int p = atomicAdd(&g_rcnt, 1);
            g_rlist[p] = rbase + tid;
        }
    }
}

// ---------------------------------------------------------------------------
// Kernel 4: exact fp32 rescue — GROUPS OF 8 rows per block sweep.
// 8 partition blocks per group (256 codes each); per d-quad: 4 coalesced LDG
// (e columns) feed 32 FMA across 8 rows (x broadcast via LDS.128).
// Merge via packed-key warp shuffle + atomicMax.
// ---------------------------------------------------------------------------
__global__ __launch_bounds__(256) void k_rescue(const float* __restrict__ x) {
    __shared__ float sx[8][256];
    __shared__ unsigned long long swk[8][8];   // [row][warp]
    const int tid = threadIdx.x;
    const int lane = tid & 31, wid = tid >> 5;
    const int part = blockIdx.x & 7;
    const int slot = blockIdx.x >> 3;          // 0..127
    const int total = g_rcnt;

    for (int g0 = slot * 8; g0 < total; g0 += 128 * 8) {
        const int m = min(8, total - g0);
        __syncthreads();                       // smem reuse guard
#pragma unroll
        for (int j = 0; j < 8; ++j) {
            int n = g_rlist[g0 + (j < m ? j : 0)];
            int b = n >> 10, hw = n & 1023;
            sx[j][tid] = x[((size_t)b * Dd + tid) * HWp + hw];
        }
        __syncthreads();

        const int k = part * 256 + tid;
        const float* col = g_EfT + k;
        float a[8];
#pragma unroll
        for (int j = 0; j < 8; ++j) a[j] = 0.f;
        for (int d = 0; d < Dd; d += 4) {
            float e0 = col[(size_t)d * Kk];
            float e1 = col[(size_t)(d + 1) * Kk];
            float e2 = col[(size_t)(d + 2) * Kk];
            float e3 = col[(size_t)(d + 3) * Kk];
#pragma unroll
            for (int j = 0; j < 8; ++j) {
                float4 xv = *(const float4*)&sx[j][d];   // broadcast LDS.128
                a[j] = fmaf(xv.x, e0, a[j]);
                a[j] = fmaf(xv.y, e1, a[j]);
                a[j] = fmaf(xv.z, e2, a[j]);
                a[j] = fmaf(xv.w, e3, a[j]);
            }
        }
        // per-row packed-key reduction: warp shuffle then cross-warp
#pragma unroll
        for (int j = 0; j < 8; ++j) {
            unsigned long long key =
                ((unsigned long long)f32_sortable(a[j]) << 32) |
                (unsigned long long)(uint32_t)(2047 - k);
#pragma unroll
            for (int off = 16; off > 0; off >>= 1) {
                unsigned long long o = __shfl_xor_sync(0xffffffffu, key, off);
                if (o > key) key = o;
            }
            if (lane == 0) swk[j][wid] = key;
        }
        __syncthreads();
        if (tid < m) {
            unsigned long long best = swk[tid][0];
#pragma unroll
            for (int w = 1; w < 8; ++w)
                if (swk[tid][w] > best) best = swk[tid][w];
            atomicMax(&g_best[g_rlist[g0 + tid]], best);
        }
    }
}

// ---------------------------------------------------------------------------
// Kernel 5: unpack rescue winners into g_idx.
// ---------------------------------------------------------------------------
__global__ void k_pick() {
    const int total = g_rcnt;
    for (int t = blockIdx.x * 256 + threadIdx.x; t < total; t += gridDim.x * 256) {
        int n = g_rlist[t];
        g_idx[n] = 2047 - (int)(uint32_t)(g_best[n] & 0xFFFFFFFFULL);
    }
}

// ---------------------------------------------------------------------------
// Kernel 6: gather + fused MSE partials + histogram + index output.
// ---------------------------------------------------------------------------
__global__ void k_gather(const float* __restrict__ x, const float* __restrict__ E,
                         float* __restrict__ out, int extras) {
    __shared__ float red[256];
    const int tid = threadIdx.x;
    const int n0 = blockIdx.x * 1024 + tid * 4;
    const int q = blockIdx.y;
    const int d0 = q * 32;
    const int4 idx4 = *(const int4*)&g_idx[n0];
    const int b = n0 >> 10;
    const int hw = n0 & 1023;

    const float* xb = x + ((size_t)b * Dd + d0) * HWp + hw;
    float* ob = out + ((size_t)b * Dd + d0) * HWp + hw;

    float acc = 0.f;
#pragma unroll 4
    for (int d = 0; d < 32; ++d) {
        const float* Er = E + (size_t)(d0 + d) * Kk;
        float4 xv = *(const float4*)&xb[(size_t)d * HWp];
        float4 qv = make_float4(Er[idx4.x], Er[idx4.y], Er[idx4.z], Er[idx4.w]);
        *(float4*)&ob[(size_t)d * HWp] = qv;
        float dx = xv.x - qv.x, dy = xv.y - qv.y;
        float dz = xv.z - qv.z, dw = xv.w - qv.w;
        acc = fmaf(dx, dx, acc); acc = fmaf(dy, dy, acc);
        acc = fmaf(dz, dz, acc); acc = fmaf(dw, dw, acc);
    }
    if (q == 0) {
        atomicAdd(&g_hist[idx4.x], 1);
        atomicAdd(&g_hist[idx4.y], 1);
        atomicAdd(&g_hist[idx4.z], 1);
        atomicAdd(&g_hist[idx4.w], 1);
        if (extras) {
            out[Q_ELEMS + 3 + n0 + 0] = (float)idx4.x;
            out[Q_ELEMS + 3 + n0 + 1] = (float)idx4.y;
            out[Q_ELEMS + 3 + n0 + 2] = (float)idx4.z;
            out[Q_ELEMS + 3 + n0 + 3] = (float)idx4.w;
        }
    }

    red[tid] = acc;
    __syncthreads();
    for (int s = 128; s > 0; s >>= 1) {
        if (tid < s) red[tid] += red[tid + s];
        __syncthreads();
    }
    if (tid == 0) g_part[blockIdx.x * 8 + q] = red[0];
}

// ---------------------------------------------------------------------------
// Kernel 7: finalize scalars
// ---------------------------------------------------------------------------
__global__ void k_final(float* __restrict__ out, int extras) {
    __shared__ float red[256];
    const int tid = threadIdx.x;

    red[tid] = g_part[tid];
    __syncthreads();
    for (int s = 128; s > 0; s >>= 1) {
        if (tid < s) red[tid] += red[tid + s];
        __syncthreads();
    }
    float mse = red[0] / (float)Q_ELEMS;
    __syncthreads();

    float e = 0.f;
    for (int bin = tid; bin < Kk; bin += 256) {
        float p = (float)g_hist[bin] / (float)Nn;
        e += p * logf(p + 1e-10f);
    }
    red[tid] = e;
    __syncthreads();
    for (int s = 128; s > 0; s >>= 1) {
        if (tid < s) red[tid] += red[tid + s];
        __syncthreads();
    }
    if (tid == 0 && extras) {
        out[Q_ELEMS + 0] = mse;
        out[Q_ELEMS + 1] = mse;
        out[Q_ELEMS + 2] = red[0];
    }
}

// ---------------------------------------------------------------------------
extern "C" void kernel_launch(void* const* d_in, const int* in_sizes, int n_in,
                              void* d_out, int out_size) {
    const float* x = (const float*)d_in[0];   // [32,256,32,32]
    const float* E = (const float*)d_in[1];   // [256,2048]
    float* out = (float*)d_out;
    const int extras = (out_size >= FULL_OUT) ? 1 : 0;

    k_invnorm<<<Kk / 256, 256>>>(E);
    k_prepe<<<dim3(Kk / 64, Dd / 64), 256>>>(E);

    cudaFuncSetAttribute(k_mma_argmax,
                         cudaFuncAttributeMaxDynamicSharedMemorySize, SM_TOT);
    k_mma_argmax<<<Nn / 64, 256, SM_TOT>>>(x);

    k_rescue<<<1024, 256>>>(x);
    k_pick<<<4, 256>>>();
    k_gather<<<dim3(Nn / 1024, 8), 256>>>(x, E, out, extras);
    k_final<<<1, 256>>>(out, extras);
}

// round 16
// speedup vs baseline: 1.3567x; 1.3567x over previous
#include <cuda_runtime.h>
#include <cuda_bf16.h>
#include <cstdint>
#include <math.h>

#define Bx 32
#define Dd 256
#define Kk 2048
#define Nn 32768
#define HWp 1024

#define Q_ELEMS   8388608
#define FULL_OUT  8421379
#define TAU       1e-4f

// ---- device scratch (no dynamic allocations allowed) ----
__device__ __nv_bfloat16 g_BhiT[Dd * Kk];   // 1 MB [D][K] normalized hi
__device__ __nv_bfloat16 g_BloT[Dd * Kk];   // 1 MB
__device__ float g_EfT[Dd * Kk];            // 2 MB [D][K] normalized fp32 (rescue)
__device__ float g_inv[Kk];
__device__ int   g_idx[Nn];
__device__ int   g_hist[Kk];
__device__ float g_part[256];
__device__ int   g_rcnt;
__device__ int   g_rlist[Nn];
__device__ unsigned long long g_best[Nn];   // packed (sortable score | 2047-idx)

// ======================= PTX helpers (compute_80+ baseline) ================
__device__ __forceinline__ uint32_t smem_u32(const void* p) {
    uint32_t a;
    asm("{ .reg .u64 t; cvta.to.shared.u64 t, %1; cvt.u32.u64 %0, t; }" : "=r"(a) : "l"(p));
    return a;
}
__device__ __forceinline__ void ldsm_x4(uint32_t* r, uint32_t addr) {
    asm volatile("ldmatrix.sync.aligned.m8n8.x4.shared.b16 {%0,%1,%2,%3}, [%4];"
        : "=r"(r[0]), "=r"(r[1]), "=r"(r[2]), "=r"(r[3]) : "r"(addr));
}
__device__ __forceinline__ void ldsm_x4_t(uint32_t* r, uint32_t addr) {
    asm volatile("ldmatrix.sync.aligned.m8n8.x4.trans.shared.b16 {%0,%1,%2,%3}, [%4];"
        : "=r"(r[0]), "=r"(r[1]), "=r"(r[2]), "=r"(r[3]) : "r"(addr));
}
__device__ __forceinline__ void mma_bf16(float* c, const uint32_t* a, const uint32_t* b) {
    asm("mma.sync.aligned.m16n8k16.row.col.f32.bf16.bf16.f32 "
        "{%0,%1,%2,%3}, {%4,%5,%6,%7}, {%8,%9}, {%0,%1,%2,%3};"
        : "+f"(c[0]), "+f"(c[1]), "+f"(c[2]), "+f"(c[3])
        : "r"(a[0]), "r"(a[1]), "r"(a[2]), "r"(a[3]), "r"(b[0]), "r"(b[1]));
}
__device__ __forceinline__ void cp_async16(uint32_t dst, const void* src) {
    asm volatile("cp.async.cg.shared.global [%0], [%1], 16;" :: "r"(dst), "l"(src) : "memory");
}
#define CP_COMMIT() asm volatile("cp.async.commit_group;" ::: "memory")
#define CP_WAIT1()  asm volatile("cp.async.wait_group 1;" ::: "memory")

__device__ __forceinline__ uint32_t f32_sortable(float f) {
    uint32_t b = __float_as_uint(f);
    return (b & 0x80000000u) ? ~b : (b | 0x80000000u);
}

// ---------------------------------------------------------------------------
// Kernel 1: per-column inverse norms + zero histogram + reset rescue count
// ---------------------------------------------------------------------------
__global__ void k_invnorm(const float* __restrict__ E) {
    int k = blockIdx.x * blockDim.x + threadIdx.x;
    float ss = 0.f;
#pragma unroll 8
    for (int d = 0; d < Dd; ++d) { float v = E[d * Kk + k]; ss = fmaf(v, v, ss); }
    g_inv[k] = 1.0f / fmaxf(sqrtf(ss), 1e-12f);
    g_hist[k] = 0;
    if (k == 0) g_rcnt = 0;
}

// ---------------------------------------------------------------------------
// Kernel 2: codebook prep: E [D,K] -> g_EfT [D][K] fp32 normalized (coalesced),
//           g_BhiT/g_BloT [D][K] bf16 split
// ---------------------------------------------------------------------------
__global__ __launch_bounds__(256) void k_prepe(const float* __restrict__ E) {
    __shared__ float t[64][65];
    const int tid = threadIdx.x;
    const int k0 = blockIdx.x * 64, d0 = blockIdx.y * 64;
#pragma unroll
    for (int i = 0; i < 16; ++i) {
        int idx = i * 256 + tid, di = idx >> 6, ki = idx & 63;
        t[di][ki] = E[(size_t)(d0 + di) * Kk + k0 + ki] * g_inv[k0 + ki];
    }
    __syncthreads();
#pragma unroll
    for (int i = 0; i < 16; ++i) {
        int idx = i * 256 + tid, ki = idx >> 6, di = idx & 63;
        g_EfT[(size_t)(d0 + di) * Kk + k0 + ki] = t[di][ki];
    }
#pragma unroll
    for (int i = 0; i < 8; ++i) {
        int idx = i * 256 + tid;
        int di = idx >> 5;
        int ki = (idx & 31) * 2;
        float v0 = t[di][ki], v1 = t[di][ki + 1];
        __nv_bfloat16 h0 = __float2bfloat16(v0);
        __nv_bfloat16 h1 = __float2bfloat16(v1);
        float l0 = v0 - __bfloat162float(h0);
        float l1 = v1 - __bfloat162float(h1);
        size_t o = (size_t)(d0 + di) * Kk + k0 + ki;
        __nv_bfloat162 hh; hh.x = h0; hh.y = h1;
        __nv_bfloat162 ll; ll.x = __float2bfloat16(l0); ll.y = __float2bfloat16(l1);
        *reinterpret_cast<__nv_bfloat162*>(&g_BhiT[o]) = hh;
        *reinterpret_cast<__nv_bfloat162*>(&g_BloT[o]) = ll;
    }
}

// ---------------------------------------------------------------------------
// Kernel 3: warp-MMA split-3 bf16 GEMM + top-2 argmax with a 3-stage
// cp.async pipeline: per iteration  wait_group(1) -> barrier -> issue
// chunk i+2 -> MMA chunk i.  The wait targets a chunk issued two iterations
// ago (already landed), so B-load latency is fully hidden under MMAs.
// A (hi+lo) = 64KB; B = 3 x 16KB stages; RED overlaps B after the loop.
// 112.6KB smem -> 2 CTAs/SM.
// ---------------------------------------------------------------------------
#define SM_ALO 32768
#define SM_B   65536
#define SM_TOT 114688

__global__ __launch_bounds__(256, 2) void k_mma_argmax(const float* __restrict__ x) {
    extern __shared__ char sm[];
    const uint32_t sb = smem_u32(sm);
    const int tid = threadIdx.x;
    const int lane = tid & 31;
    const int wid = tid >> 5;
    const int wm = wid & 1, wn = wid >> 1;
    const int rbase = blockIdx.x * 64;
    const int b = rbase >> 10, hw0 = rbase & 1023;
    const int ldr = tid >> 4, ldu = tid & 15;

    // ---- build A (hi+lo, swizzled [row][d]) from raw x (staging in B area) ----
    {
        float* stg = (float*)(sm + SM_B);
#pragma unroll
        for (int h = 0; h < 2; ++h) {
            __syncthreads();
#pragma unroll
            for (int i = 0; i < 8; ++i) {
                int idx = i * 256 + tid;
                int d = idx >> 4, r4 = idx & 15;
                float4 v = *(const float4*)(x + ((size_t)b * Dd + h * 128 + d) * HWp + hw0 + r4 * 4);
                *(float4*)&stg[d * 68 + r4 * 4] = v;
            }
            __syncthreads();
#pragma unroll
            for (int it = 0; it < 4; ++it) {
                int idx = it * 256 + tid;
                int r = idx & 63, u = idx >> 6;
                float f[8];
#pragma unroll
                for (int j = 0; j < 8; ++j) f[j] = stg[(u * 8 + j) * 68 + r];
                uint32_t hi[4], lo[4];
#pragma unroll
                for (int q = 0; q < 4; ++q) {
                    __nv_bfloat16 h0 = __float2bfloat16(f[2 * q]);
                    __nv_bfloat16 h1 = __float2bfloat16(f[2 * q + 1]);
                    __nv_bfloat162 hh; hh.x = h0; hh.y = h1;
                    hi[q] = *reinterpret_cast<uint32_t*>(&hh);
                    __nv_bfloat162 llp;
                    llp.x = __float2bfloat16(f[2 * q] - __bfloat162float(h0));
                    llp.y = __float2bfloat16(f[2 * q + 1] - __bfloat162float(h1));
                    lo[q] = *reinterpret_cast<uint32_t*>(&llp);
                }
                int ug = h * 16 + u;
                uint32_t ad = r * 512 + ((ug ^ (r & 7)) << 4);
                *(uint4*)(sm + ad) = make_uint4(hi[0], hi[1], hi[2], hi[3]);
                *(uint4*)(sm + SM_ALO + ad) = make_uint4(lo[0], lo[1], lo[2], lo[3]);
            }
        }
        __syncthreads();   // A complete; B region free for the pipeline
    }

    // chunk c layout: ct = c>>3, kc = c&7; stage = c%3 at SM_B + stage*16384
    // hi at +0, lo at +8192 within a stage.
    auto issue_chunk = [&](int c) {
        int ct = c >> 3, kc = c & 7;
        uint32_t stbase = sb + SM_B + (uint32_t)(c % 3) * 16384;
#pragma unroll
        for (int j = 0; j < 2; ++j) {
            int r = j * 16 + ldr;
            size_t so = ((size_t)(kc * 32 + r) * Kk + ct * 128) * 2 + (size_t)ldu * 16;
            uint32_t dst = stbase + r * 256 + ((ldu ^ (r & 7)) << 4);
            cp_async16(dst, (const char*)g_BhiT + so);
            cp_async16(dst + 8192, (const char*)g_BloT + so);
        }
    };

    // prologue: two chunks in flight
    issue_chunk(0); CP_COMMIT();
    issue_chunk(1); CP_COMMIT();

    float c[2][4][4];
#pragma unroll
    for (int mi = 0; mi < 2; ++mi)
#pragma unroll
        for (int j = 0; j < 4; ++j)
#pragma unroll
            for (int q = 0; q < 4; ++q) c[mi][j][q] = 0.f;

    float v1[4], v2[4];
    int   i1[4];
#pragma unroll
    for (int s = 0; s < 4; ++s) { v1[s] = -3.0e38f; v2[s] = -3.0e38f; i1[s] = 0; }

    const int kk = (lane & 7) + ((lane >> 3) & 1) * 8;

    for (int cid = 0; cid < 128; ++cid) {
        const int ct = cid >> 3, kc = cid & 7;

        CP_WAIT1();          // chunk cid (issued 2 iters ago) has landed
        __syncthreads();     // all threads' copies visible; stage reuse safe

        // issue chunk cid+2 into stage (cid+2)%3 (held chunk cid-1; all
        // threads passed the barrier after finishing its MMAs)
        if (cid + 2 < 128) issue_chunk(cid + 2);
        CP_COMMIT();

        const uint32_t bbase = sb + SM_B + (uint32_t)(cid % 3) * 16384;
#pragma unroll
        for (int kcs = 0; kcs < 2; ++kcs) {
            uint32_t ah[2][4], al[2][4];
#pragma unroll
            for (int mi = 0; mi < 2; ++mi) {
                int r0 = wm * 32 + mi * 16 + (lane & 15);
                int u0 = kc * 4 + kcs * 2 + (lane >> 4);
                uint32_t aaddr = sb + r0 * 512 + ((u0 ^ (r0 & 7)) << 4);
                ldsm_x4(ah[mi], aaddr);
                ldsm_x4(al[mi], aaddr + SM_ALO);
            }
            uint32_t bh[2][4], bl[2][4];
#pragma unroll
            for (int p = 0; p < 2; ++p) {
                int u0 = wn * 4 + p * 2 + (lane >> 4);
                uint32_t baddr = bbase + kcs * 4096 + kk * 256 + ((u0 ^ (kk & 7)) << 4);
                ldsm_x4_t(bh[p], baddr);
                ldsm_x4_t(bl[p], baddr + 8192);
            }
            // ---- 24 HMMA: hi*hi + hi*lo + lo*hi ----
#pragma unroll
            for (int mi = 0; mi < 2; ++mi)
#pragma unroll
                for (int p = 0; p < 2; ++p) {
                    mma_bf16(c[mi][2 * p],     ah[mi], &bh[p][0]);
                    mma_bf16(c[mi][2 * p + 1], ah[mi], &bh[p][2]);
                    mma_bf16(c[mi][2 * p],     ah[mi], &bl[p][0]);
                    mma_bf16(c[mi][2 * p + 1], ah[mi], &bl[p][2]);
                    mma_bf16(c[mi][2 * p],     al[mi], &bh[p][0]);
                    mma_bf16(c[mi][2 * p + 1], al[mi], &bh[p][2]);
                }
        }

        if (kc == 7) {
            const int cb = ct * 128 + wn * 32 + (lane & 3) * 2;
#pragma unroll
            for (int mi = 0; mi < 2; ++mi)
#pragma unroll
                for (int j = 0; j < 4; ++j)
#pragma unroll
                    for (int q = 0; q < 4; ++q) {
                        float v = c[mi][j][q];
                        int col = cb + j * 8 + (q & 1);
                        int slot = mi * 2 + (q >> 1);
                        if (v > v1[slot]) { v2[slot] = v1[slot]; v1[slot] = v; i1[slot] = col; }
                        else if (v > v2[slot]) { v2[slot] = v; }
                        c[mi][j][q] = 0.f;
                    }
        }
    }

    __syncthreads();   // all MMAs done before RED overlays the B stages

#pragma unroll
    for (int s = 0; s < 4; ++s) {
#pragma unroll
        for (int m = 1; m <= 2; m <<= 1) {
            float ov1 = __shfl_xor_sync(0xffffffffu, v1[s], m);
            float ov2 = __shfl_xor_sync(0xffffffffu, v2[s], m);
            int   oi1 = __shfl_xor_sync(0xffffffffu, i1[s], m);
            if (ov1 > v1[s]) { v2[s] = fmaxf(v1[s], ov2); v1[s] = ov1; i1[s] = oi1; }
            else             { v2[s] = fmaxf(v2[s], ov1); }
        }
    }
    float* sv1 = (float*)(sm + SM_B);
    float* sv2 = (float*)(sm + SM_B + 1024);
    int*   si1 = (int*)  (sm + SM_B + 2048);
    if ((lane & 3) == 0) {
#pragma unroll
        for (int s = 0; s < 4; ++s) {
            int row = wm * 32 + (s >> 1) * 16 + (s & 1) * 8 + (lane >> 2);
            sv1[row * 4 + wn] = v1[s];
            sv2[row * 4 + wn] = v2[s];
            si1[row * 4 + wn] = i1[s];
        }
    }
    __syncthreads();
    if (tid < 64) {
        float t1 = -3.0e38f, t2 = -3.0e38f;
        int ti = 0;
#pragma unroll
        for (int p = 0; p < 4; ++p) {
            float a1 = sv1[tid * 4 + p], a2 = sv2[tid * 4 + p];
            int ai = si1[tid * 4 + p];
            if (a1 > t1) { t2 = fmaxf(t1, a2); t1 = a1; ti = ai; }
            else         { t2 = fmaxf(t2, a1); }
        }
        g_idx[rbase + tid] = ti;
        if (t1 - t2 < TAU) {
            g_best[rbase + tid] = 0ULL;          // floor for atomicMax keys
            int p = atomicAdd(&g_rcnt, 1);
            g_rlist[p] = rbase + tid;
        }
    }
}

// ---------------------------------------------------------------------------
// Kernel 4: exact fp32 rescue — groups of 8 rows per sweep, 8 partition
// blocks (256 codes each); packed-key shuffle merge + atomicMax.
// ---------------------------------------------------------------------------
__global__ __launch_bounds__(256) void k_rescue(const float* __restrict__ x) {
    __shared__ float sx[8][256];
    __shared__ unsigned long long swk[8][8];   // [row][warp]
    const int tid = threadIdx.x;
    const int lane = tid & 31, wid = tid >> 5;
    const int part = blockIdx.x & 7;
    const int slot = blockIdx.x >> 3;          // 0..127
    const int total = g_rcnt;

    for (int g0 = slot * 8; g0 < total; g0 += 128 * 8) {
        const int m = min(8, total - g0);
        __syncthreads();                       // smem reuse guard
#pragma unroll
        for (int j = 0; j < 8; ++j) {
            int n = g_rlist[g0 + (j < m ? j : 0)];
            int b = n >> 10, hw = n & 1023;
            sx[j][tid] = x[((size_t)b * Dd + tid) * HWp + hw];
        }
        __syncthreads();

        const int k = part * 256 + tid;
        const float* col = g_EfT + k;
        float a[8];
#pragma unroll
        for (int j = 0; j < 8; ++j) a[j] = 0.f;
        for (int d = 0; d < Dd; d += 4) {
            float e0 = col[(size_t)d * Kk];
            float e1 = col[(size_t)(d + 1) * Kk];
            float e2 = col[(size_t)(d + 2) * Kk];
            float e3 = col[(size_t)(d + 3) * Kk];
#pragma unroll
            for (int j = 0; j < 8; ++j) {
                float4 xv = *(const float4*)&sx[j][d];
                a[j] = fmaf(xv.x, e0, a[j]);
                a[j] = fmaf(xv.y, e1, a[j]);
                a[j] = fmaf(xv.z, e2, a[j]);
                a[j] = fmaf(xv.w, e3, a[j]);
            }
        }
#pragma unroll
        for (int j = 0; j < 8; ++j) {
            unsigned long long key =
                ((unsigned long long)f32_sortable(a[j]) << 32) |
                (unsigned long long)(uint32_t)(2047 - k);
#pragma unroll
            for (int off = 16; off > 0; off >>= 1) {
                unsigned long long o = __shfl_xor_sync(0xffffffffu, key, off);
                if (o > key) key = o;
            }
            if (lane == 0) swk[j][wid] = key;
        }
        __syncthreads();
        if (tid < m) {
            unsigned long long best = swk[tid][0];
#pragma unroll
            for (int w = 1; w < 8; ++w)
                if (swk[tid][w] > best) best = swk[tid][w];
            atomicMax(&g_best[g_rlist[g0 + tid]], best);
        }
    }
}

// ---------------------------------------------------------------------------
// Kernel 5: unpack rescue winners into g_idx.
// ---------------------------------------------------------------------------
__global__ void k_pick() {
    const int total = g_rcnt;
    for (int t = blockIdx.x * 256 + threadIdx.x; t < total; t += gridDim.x * 256) {
        int n = g_rlist[t];
        g_idx[n] = 2047 - (int)(uint32_t)(g_best[n] & 0xFFFFFFFFULL);
    }
}

// ---------------------------------------------------------------------------
// Kernel 6: gather + fused MSE partials + histogram + index output.
// ---------------------------------------------------------------------------
__global__ void k_gather(const float* __restrict__ x, const float* __restrict__ E,
                         float* __restrict__ out, int extras) {
    __shared__ float red[256];
    const int tid = threadIdx.x;
    const int n0 = blockIdx.x * 1024 + tid * 4;
    const int q = blockIdx.y;
    const int d0 = q * 32;
    const int4 idx4 = *(const int4*)&g_idx[n0];
    const int b = n0 >> 10;
    const int hw = n0 & 1023;

    const float* xb = x + ((size_t)b * Dd + d0) * HWp + hw;
    float* ob = out + ((size_t)b * Dd + d0) * HWp + hw;

    float acc = 0.f;
#pragma unroll 4
    for (int d = 0; d < 32; ++d) {
        const float* Er = E + (size_t)(d0 + d) * Kk;
        float4 xv = *(const float4*)&xb[(size_t)d * HWp];
        float4 qv = make_float4(Er[idx4.x], Er[idx4.y], Er[idx4.z], Er[idx4.w]);
        *(float4*)&ob[(size_t)d * HWp] = qv;
        float dx = xv.x - qv.x, dy = xv.y - qv.y;
        float dz = xv.z - qv.z, dw = xv.w - qv.w;
        acc = fmaf(dx, dx, acc); acc = fmaf(dy, dy, acc);
        acc = fmaf(dz, dz, acc); acc = fmaf(dw, dw, acc);
    }
    if (q == 0) {
        atomicAdd(&g_hist[idx4.x], 1);
        atomicAdd(&g_hist[idx4.y], 1);
        atomicAdd(&g_hist[idx4.z], 1);
        atomicAdd(&g_hist[idx4.w], 1);
        if (extras) {
            out[Q_ELEMS + 3 + n0 + 0] = (float)idx4.x;
            out[Q_ELEMS + 3 + n0 + 1] = (float)idx4.y;
            out[Q_ELEMS + 3 + n0 + 2] = (float)idx4.z;
            out[Q_ELEMS + 3 + n0 + 3] = (float)idx4.w;
        }
    }

    red[tid] = acc;
    __syncthreads();
    for (int s = 128; s > 0; s >>= 1) {
        if (tid < s) red[tid] += red[tid + s];
        __syncthreads();
    }
    if (tid == 0) g_part[blockIdx.x * 8 + q] = red[0];
}

// ---------------------------------------------------------------------------
// Kernel 7: finalize scalars
// ---------------------------------------------------------------------------
__global__ void k_final(float* __restrict__ out, int extras) {
    __shared__ float red[256];
    const int tid = threadIdx.x;

    red[tid] = g_part[tid];
    __syncthreads();
    for (int s = 128; s > 0; s >>= 1) {
        if (tid < s) red[tid] += red[tid + s];
        __syncthreads();
    }
    float mse = red[0] / (float)Q_ELEMS;
    __syncthreads();

    float e = 0.f;
    for (int bin = tid; bin < Kk; bin += 256) {
        float p = (float)g_hist[bin] / (float)Nn;
        e += p * logf(p + 1e-10f);
    }
    red[tid] = e;
    __syncthreads();
    for (int s = 128; s > 0; s >>= 1) {
        if (tid < s) red[tid] += red[tid + s];
        __syncthreads();
    }
    if (tid == 0 && extras) {
        out[Q_ELEMS + 0] = mse;
        out[Q_ELEMS + 1] = mse;
        out[Q_ELEMS + 2] = red[0];
    }
}

// ---------------------------------------------------------------------------
extern "C" void kernel_launch(void* const* d_in, const int* in_sizes, int n_in,
                              void* d_out, int out_size) {
    const float* x = (const float*)d_in[0];   // [32,256,32,32]
    const float* E = (const float*)d_in[1];   // [256,2048]
    float* out = (float*)d_out;
    const int extras = (out_size >= FULL_OUT) ? 1 : 0;

    k_invnorm<<<Kk / 256, 256>>>(E);
    k_prepe<<<dim3(Kk / 64, Dd / 64), 256>>>(E);

    cudaFuncSetAttribute(k_mma_argmax,
                         cudaFuncAttributeMaxDynamicSharedMemorySize, SM_TOT);
    k_mma_argmax<<<Nn / 64, 256, SM_TOT>>>(x);

    k_rescue<<<1024, 256>>>(x);
    k_pick<<<4, 256>>>();
    k_gather<<<dim3(Nn / 1024, 8), 256>>>(x, E, out, extras);
    k_final<<<1, 256>>>(out, extras);
}

// round 17
// speedup vs baseline: 1.5903x; 1.1721x over previous
#include <cuda_runtime.h>
#include <cuda_bf16.h>
#include <cstdint>
#include <math.h>

#define Bx 32
#define Dd 256
#define Kk 2048
#define Nn 32768
#define HWp 1024

#define Q_ELEMS   8388608
#define FULL_OUT  8421379
#define TAU       1e-2f

// ---- device scratch (no dynamic allocations allowed) ----
__device__ __nv_bfloat16 g_BhiT[Dd * Kk];   // 1 MB [D][K] normalized hi
__device__ __nv_bfloat16 g_BloT[Dd * Kk];   // 1 MB
__device__ float g_EfT[Dd * Kk];            // 2 MB [D][K] normalized fp32 (rescue)
__device__ float g_inv[Kk];
__device__ int   g_idx[Nn];
__device__ int   g_hist[Kk];
__device__ float g_part[256];
__device__ int   g_rcnt;
__device__ int   g_rlist[Nn];
__device__ unsigned long long g_best[Nn];   // packed (sortable score | 2047-idx)

// ======================= PTX helpers (compute_80+ baseline) ================
__device__ __forceinline__ uint32_t smem_u32(const void* p) {
    uint32_t a;
    asm("{ .reg .u64 t; cvta.to.shared.u64 t, %1; cvt.u32.u64 %0, t; }" : "=r"(a) : "l"(p));
    return a;
}
__device__ __forceinline__ void ldsm_x4(uint32_t* r, uint32_t addr) {
    asm volatile("ldmatrix.sync.aligned.m8n8.x4.shared.b16 {%0,%1,%2,%3}, [%4];"
        : "=r"(r[0]), "=r"(r[1]), "=r"(r[2]), "=r"(r[3]) : "r"(addr));
}
__device__ __forceinline__ void ldsm_x4_t(uint32_t* r, uint32_t addr) {
    asm volatile("ldmatrix.sync.aligned.m8n8.x4.trans.shared.b16 {%0,%1,%2,%3}, [%4];"
        : "=r"(r[0]), "=r"(r[1]), "=r"(r[2]), "=r"(r[3]) : "r"(addr));
}
__device__ __forceinline__ void mma_bf16(float* c, const uint32_t* a, const uint32_t* b) {
    asm("mma.sync.aligned.m16n8k16.row.col.f32.bf16.bf16.f32 "
        "{%0,%1,%2,%3}, {%4,%5,%6,%7}, {%8,%9}, {%0,%1,%2,%3};"
        : "+f"(c[0]), "+f"(c[1]), "+f"(c[2]), "+f"(c[3])
        : "r"(a[0]), "r"(a[1]), "r"(a[2]), "r"(a[3]), "r"(b[0]), "r"(b[1]));
}
__device__ __forceinline__ void cp_async16(uint32_t dst, const void* src) {
    asm volatile("cp.async.cg.shared.global [%0], [%1], 16;" :: "r"(dst), "l"(src) : "memory");
}
#define CP_COMMIT() asm volatile("cp.async.commit_group;" ::: "memory")
#define CP_WAIT0()  asm volatile("cp.async.wait_group 0;" ::: "memory")

__device__ __forceinline__ uint32_t f32_sortable(float f) {
    uint32_t b = __float_as_uint(f);
    return (b & 0x80000000u) ? ~b : (b | 0x80000000u);
}

// ---------------------------------------------------------------------------
// Kernel 1: per-column inverse norms + zero histogram + reset rescue count
// ---------------------------------------------------------------------------
__global__ void k_invnorm(const float* __restrict__ E) {
    int k = blockIdx.x * blockDim.x + threadIdx.x;
    float ss = 0.f;
#pragma unroll 8
    for (int d = 0; d < Dd; ++d) { float v = E[d * Kk + k]; ss = fmaf(v, v, ss); }
    g_inv[k] = 1.0f / fmaxf(sqrtf(ss), 1e-12f);
    g_hist[k] = 0;
    if (k == 0) g_rcnt = 0;
}

// ---------------------------------------------------------------------------
// Kernel 2: codebook prep: E [D,K] -> g_EfT [D][K] fp32 normalized (coalesced),
//           g_BhiT/g_BloT [D][K] bf16 split
// ---------------------------------------------------------------------------
__global__ __launch_bounds__(256) void k_prepe(const float* __restrict__ E) {
    __shared__ float t[64][65];
    const int tid = threadIdx.x;
    const int k0 = blockIdx.x * 64, d0 = blockIdx.y * 64;
#pragma unroll
    for (int i = 0; i < 16; ++i) {
        int idx = i * 256 + tid, di = idx >> 6, ki = idx & 63;
        t[di][ki] = E[(size_t)(d0 + di) * Kk + k0 + ki] * g_inv[k0 + ki];
    }
    __syncthreads();
#pragma unroll
    for (int i = 0; i < 16; ++i) {
        int idx = i * 256 + tid, ki = idx >> 6, di = idx & 63;
        g_EfT[(size_t)(d0 + di) * Kk + k0 + ki] = t[di][ki];
    }
#pragma unroll
    for (int i = 0; i < 8; ++i) {
        int idx = i * 256 + tid;
        int di = idx >> 5;
        int ki = (idx & 31) * 2;
        float v0 = t[di][ki], v1 = t[di][ki + 1];
        __nv_bfloat16 h0 = __float2bfloat16(v0);
        __nv_bfloat16 h1 = __float2bfloat16(v1);
        float l0 = v0 - __bfloat162float(h0);
        float l1 = v1 - __bfloat162float(h1);
        size_t o = (size_t)(d0 + di) * Kk + k0 + ki;
        __nv_bfloat162 hh; hh.x = h0; hh.y = h1;
        __nv_bfloat162 ll; ll.x = __float2bfloat16(l0); ll.y = __float2bfloat16(l1);
        *reinterpret_cast<__nv_bfloat162*>(&g_BhiT[o]) = hh;
        *reinterpret_cast<__nv_bfloat162*>(&g_BloT[o]) = ll;
    }
}

// ---------------------------------------------------------------------------
// Kernel 3: warp-MMA split-2 bf16 GEMM + top-2 argmax (R14-proven).
// scores = x_hi · (e_hi + e_lo); dropped x_lo·e_hi term (err std ~1.7e-3)
// absorbed by exact rescue with TAU=1e-2 (~6 sigma). A = x_hi only (32KB)
// -> 67KB smem, 3 CTAs/SM.
// ---------------------------------------------------------------------------
#define SM_B   32768
#define SM_RED 65536
#define SM_TOT 68608

__global__ __launch_bounds__(256, 3) void k_mma_argmax(const float* __restrict__ x) {
    extern __shared__ char sm[];
    const uint32_t sb = smem_u32(sm);
    const int tid = threadIdx.x;
    const int lane = tid & 31;
    const int wid = tid >> 5;
    const int wm = wid & 1, wn = wid >> 1;
    const int rbase = blockIdx.x * 64;
    const int b = rbase >> 10, hw0 = rbase & 1023;
    const int ldr = tid >> 4, ldu = tid & 15;

    // ---- build A (hi only, swizzled [row][d]) from raw x ----
    {
        float* stg = (float*)(sm + SM_B);
#pragma unroll
        for (int h = 0; h < 2; ++h) {
            __syncthreads();
#pragma unroll
            for (int i = 0; i < 8; ++i) {
                int idx = i * 256 + tid;
                int d = idx >> 4, r4 = idx & 15;
                float4 v = *(const float4*)(x + ((size_t)b * Dd + h * 128 + d) * HWp + hw0 + r4 * 4);
                *(float4*)&stg[d * 68 + r4 * 4] = v;
            }
            __syncthreads();
#pragma unroll
            for (int it = 0; it < 4; ++it) {
                int idx = it * 256 + tid;
                int r = idx & 63, u = idx >> 6;
                float f[8];
#pragma unroll
                for (int j = 0; j < 8; ++j) f[j] = stg[(u * 8 + j) * 68 + r];
                uint32_t hi[4];
#pragma unroll
                for (int q = 0; q < 4; ++q) {
                    __nv_bfloat162 hh;
                    hh.x = __float2bfloat16(f[2 * q]);
                    hh.y = __float2bfloat16(f[2 * q + 1]);
                    hi[q] = *reinterpret_cast<uint32_t*>(&hh);
                }
                int ug = h * 16 + u;
                uint32_t ad = r * 512 + ((ug ^ (r & 7)) << 4);
                *(uint4*)(sm + ad) = make_uint4(hi[0], hi[1], hi[2], hi[3]);
            }
        }
        __syncthreads();
    }

    // ---- kick off B chunk 0 (hi 8KB + lo 8KB) into stage 0 ----
#pragma unroll
    for (int j = 0; j < 2; ++j) {
        int r = j * 16 + ldr;
        size_t so = ((size_t)r * Kk) * 2 + (size_t)ldu * 16;
        uint32_t dst = sb + SM_B + r * 256 + ((ldu ^ (r & 7)) << 4);
        cp_async16(dst, (const char*)g_BhiT + so);
        cp_async16(dst + 8192, (const char*)g_BloT + so);
    }
    CP_COMMIT();
    CP_WAIT0();
    __syncthreads();

    float c[2][4][4];
#pragma unroll
    for (int mi = 0; mi < 2; ++mi)
#pragma unroll
        for (int j = 0; j < 4; ++j)
#pragma unroll
            for (int q = 0; q < 4; ++q) c[mi][j][q] = 0.f;

    float v1[4], v2[4];
    int   i1[4];
#pragma unroll
    for (int s = 0; s < 4; ++s) { v1[s] = -3.0e38f; v2[s] = -3.0e38f; i1[s] = 0; }

    int stage = 0;
    const int kk = (lane & 7) + ((lane >> 3) & 1) * 8;

    for (int cid = 0; cid < 128; ++cid) {
        const int ct = cid >> 3, kc = cid & 7;

        if (cid < 127) {
            int nct = (cid + 1) >> 3, nkc = (cid + 1) & 7;
#pragma unroll
            for (int j = 0; j < 2; ++j) {
                int r = j * 16 + ldr;
                size_t so = ((size_t)(nkc * 32 + r) * Kk + nct * 128) * 2 + (size_t)ldu * 16;
                uint32_t dst = sb + SM_B + (stage ^ 1) * 16384 + r * 256 + ((ldu ^ (r & 7)) << 4);
                cp_async16(dst, (const char*)g_BhiT + so);
                cp_async16(dst + 8192, (const char*)g_BloT + so);
            }
        }
        CP_COMMIT();

#pragma unroll
        for (int kcs = 0; kcs < 2; ++kcs) {
            uint32_t ah[2][4];
#pragma unroll
            for (int mi = 0; mi < 2; ++mi) {
                int r0 = wm * 32 + mi * 16 + (lane & 15);
                int u0 = kc * 4 + kcs * 2 + (lane >> 4);
                uint32_t aaddr = sb + r0 * 512 + ((u0 ^ (r0 & 7)) << 4);
                ldsm_x4(ah[mi], aaddr);
            }
            uint32_t bh[2][4], bl[2][4];
            const uint32_t bbase = sb + SM_B + stage * 16384 + kcs * 4096;
#pragma unroll
            for (int p = 0; p < 2; ++p) {
                int u0 = wn * 4 + p * 2 + (lane >> 4);
                uint32_t baddr = bbase + kk * 256 + ((u0 ^ (kk & 7)) << 4);
                ldsm_x4_t(bh[p], baddr);
                ldsm_x4_t(bl[p], baddr + 8192);
            }
            // ---- 16 HMMA: hi*(hi + lo) ----
#pragma unroll
            for (int mi = 0; mi < 2; ++mi)
#pragma unroll
                for (int p = 0; p < 2; ++p) {
                    mma_bf16(c[mi][2 * p],     ah[mi], &bh[p][0]);
                    mma_bf16(c[mi][2 * p + 1], ah[mi], &bh[p][2]);
                    mma_bf16(c[mi][2 * p],     ah[mi], &bl[p][0]);
                    mma_bf16(c[mi][2 * p + 1], ah[mi], &bl[p][2]);
                }
        }

        if (kc == 7) {
            const int cb = ct * 128 + wn * 32 + (lane & 3) * 2;
#pragma unroll
            for (int mi = 0; mi < 2; ++mi)
#pragma unroll
                for (int j = 0; j < 4; ++j)
#pragma unroll
                    for (int q = 0; q < 4; ++q) {
                        float v = c[mi][j][q];
                        int col = cb + j * 8 + (q & 1);
                        int slot = mi * 2 + (q >> 1);
                        if (v > v1[slot]) { v2[slot] = v1[slot]; v1[slot] = v; i1[slot] = col; }
                        else if (v > v2[slot]) { v2[slot] = v; }
                        c[mi][j][q] = 0.f;
                    }
        }

        CP_WAIT0();
        __syncthreads();
        stage ^= 1;
    }

#pragma unroll
    for (int s = 0; s < 4; ++s) {
#pragma unroll
        for (int m = 1; m <= 2; m <<= 1) {
            float ov1 = __shfl_xor_sync(0xffffffffu, v1[s], m);
            float ov2 = __shfl_xor_sync(0xffffffffu, v2[s], m);
            int   oi1 = __shfl_xor_sync(0xffffffffu, i1[s], m);
            if (ov1 > v1[s]) { v2[s] = fmaxf(v1[s], ov2); v1[s] = ov1; i1[s] = oi1; }
            else             { v2[s] = fmaxf(v2[s], ov1); }
        }
    }
    float* sv1 = (float*)(sm + SM_RED);
    float* sv2 = (float*)(sm + SM_RED + 1024);
    int*   si1 = (int*)  (sm + SM_RED + 2048);
    if ((lane & 3) == 0) {
#pragma unroll
        for (int s = 0; s < 4; ++s) {
            int row = wm * 32 + (s >> 1) * 16 + (s & 1) * 8 + (lane >> 2);
            sv1[row * 4 + wn] = v1[s];
            sv2[row * 4 + wn] = v2[s];
            si1[row * 4 + wn] = i1[s];
        }
    }
    __syncthreads();
    if (tid < 64) {
        float t1 = -3.0e38f, t2 = -3.0e38f;
        int ti = 0;
#pragma unroll
        for (int p = 0; p < 4; ++p) {
            float a1 = sv1[tid * 4 + p], a2 = sv2[tid * 4 + p];
            int ai = si1[tid * 4 + p];
            if (a1 > t1) { t2 = fmaxf(t1, a2); t1 = a1; ti = ai; }
            else         { t2 = fmaxf(t2, a1); }
        }
        g_idx[rbase + tid] = ti;
        if (t1 - t2 < TAU) {
            g_best[rbase + tid] = 0ULL;          // floor for atomicMax keys
            int p = atomicAdd(&g_rcnt, 1);
            g_rlist[p] = rbase + tid;
        }
    }
}

// ---------------------------------------------------------------------------
// Kernel 4: exact fp32 rescue — 8 rows x 4 codes per thread.
// 2 partition blocks per 8-row group (1024 codes each, thread owns 4 via
// float4 LDG). Per d: 1 LDG.128 + 8 broadcast LDS + 32 FMA, pointer-
// incremented (no 64-bit muls in the loop).
// ---------------------------------------------------------------------------
__global__ __launch_bounds__(256) void k_rescue(const float* __restrict__ x) {
    __shared__ float sx[8][256];
    __shared__ unsigned long long swk[8][8];   // [row][warp]
    const int tid = threadIdx.x;
    const int lane = tid & 31, wid = tid >> 5;
    const int part = blockIdx.x & 1;           // 0..1 (1024 codes each)
    const int slot = blockIdx.x >> 1;          // 0..511
    const int total = g_rcnt;

    for (int g0 = slot * 8; g0 < total; g0 += 512 * 8) {
        const int m = min(8, total - g0);
        __syncthreads();                       // smem reuse guard
#pragma unroll
        for (int j = 0; j < 8; ++j) {
            int n = g_rlist[g0 + (j < m ? j : 0)];
            int b = n >> 10, hw = n & 1023;
            sx[j][tid] = x[((size_t)b * Dd + tid) * HWp + hw];
        }
        __syncthreads();

        const int k0 = part * 1024 + tid * 4;
        const float* ep = g_EfT + k0;
        float a[8][4];
#pragma unroll
        for (int j = 0; j < 8; ++j)
#pragma unroll
            for (int q = 0; q < 4; ++q) a[j][q] = 0.f;

        for (int d = 0; d < Dd; ++d) {
            float4 e = *(const float4*)ep;
            ep += Kk;
#pragma unroll
            for (int j = 0; j < 8; ++j) {
                float xv = sx[j][d];           // broadcast LDS
                a[j][0] = fmaf(xv, e.x, a[j][0]);
                a[j][1] = fmaf(xv, e.y, a[j][1]);
                a[j][2] = fmaf(xv, e.z, a[j][2]);
                a[j][3] = fmaf(xv, e.w, a[j][3]);
            }
        }

        // per-row reduction: in-thread (ascending k, strict >) then shuffle
#pragma unroll
        for (int j = 0; j < 8; ++j) {
            float bv = a[j][0]; int bi = k0;
#pragma unroll
            for (int q = 1; q < 4; ++q)
                if (a[j][q] > bv) { bv = a[j][q]; bi = k0 + q; }
            unsigned long long key =
                ((unsigned long long)f32_sortable(bv) << 32) |
                (unsigned long long)(uint32_t)(2047 - bi);
#pragma unroll
            for (int off = 16; off > 0; off >>= 1) {
                unsigned long long o = __shfl_xor_sync(0xffffffffu, key, off);
                if (o > key) key = o;
            }
            if (lane == 0) swk[j][wid] = key;
        }
        __syncthreads();
        if (tid < m) {
            unsigned long long best = swk[tid][0];
#pragma unroll
            for (int w = 1; w < 8; ++w)
                if (swk[tid][w] > best) best = swk[tid][w];
            atomicMax(&g_best[g_rlist[g0 + tid]], best);
        }
    }
}

// ---------------------------------------------------------------------------
// Kernel 5: unpack rescue winners into g_idx.
// ---------------------------------------------------------------------------
__global__ void k_pick() {
    const int total = g_rcnt;
    for (int t = blockIdx.x * 256 + threadIdx.x; t < total; t += gridDim.x * 256) {
        int n = g_rlist[t];
        g_idx[n] = 2047 - (int)(uint32_t)(g_best[n] & 0xFFFFFFFFULL);
    }
}

// ---------------------------------------------------------------------------
// Kernel 6: gather + fused MSE partials + histogram + index output.
// ---------------------------------------------------------------------------
__global__ void k_gather(const float* __restrict__ x, const float* __restrict__ E,
                         float* __restrict__ out, int extras) {
    __shared__ float red[256];
    const int tid = threadIdx.x;
    const int n0 = blockIdx.x * 1024 + tid * 4;
    const int q = blockIdx.y;
    const int d0 = q * 32;
    const int4 idx4 = *(const int4*)&g_idx[n0];
    const int b = n0 >> 10;
    const int hw = n0 & 1023;

    const float* xb = x + ((size_t)b * Dd + d0) * HWp + hw;
    float* ob = out + ((size_t)b * Dd + d0) * HWp + hw;

    float acc = 0.f;
#pragma unroll 4
    for (int d = 0; d < 32; ++d) {
        const float* Er = E + (size_t)(d0 + d) * Kk;
        float4 xv = *(const float4*)&xb[(size_t)d * HWp];
        float4 qv = make_float4(Er[idx4.x], Er[idx4.y], Er[idx4.z], Er[idx4.w]);
        *(float4*)&ob[(size_t)d * HWp] = qv;
        float dx = xv.x - qv.x, dy = xv.y - qv.y;
        float dz = xv.z - qv.z, dw = xv.w - qv.w;
        acc = fmaf(dx, dx, acc); acc = fmaf(dy, dy, acc);
        acc = fmaf(dz, dz, acc); acc = fmaf(dw, dw, acc);
    }
    if (q == 0) {
        atomicAdd(&g_hist[idx4.x], 1);
        atomicAdd(&g_hist[idx4.y], 1);
        atomicAdd(&g_hist[idx4.z], 1);
        atomicAdd(&g_hist[idx4.w], 1);
        if (extras) {
            out[Q_ELEMS + 3 + n0 + 0] = (float)idx4.x;
            out[Q_ELEMS + 3 + n0 + 1] = (float)idx4.y;
            out[Q_ELEMS + 3 + n0 + 2] = (float)idx4.z;
            out[Q_ELEMS + 3 + n0 + 3] = (float)idx4.w;
        }
    }

    red[tid] = acc;
    __syncthreads();
    for (int s = 128; s > 0; s >>= 1) {
        if (tid < s) red[tid] += red[tid + s];
        __syncthreads();
    }
    if (tid == 0) g_part[blockIdx.x * 8 + q] = red[0];
}

// ---------------------------------------------------------------------------
// Kernel 7: finalize scalars
// ---------------------------------------------------------------------------
__global__ void k_final(float* __restrict__ out, int extras) {
    __shared__ float red[256];
    const int tid = threadIdx.x;

    red[tid] = g_part[tid];
    __syncthreads();
    for (int s = 128; s > 0; s >>= 1) {
        if (tid < s) red[tid] += red[tid + s];
        __syncthreads();
    }
    float mse = red[0] / (float)Q_ELEMS;
    __syncthreads();

    float e = 0.f;
    for (int bin = tid; bin < Kk; bin += 256) {
        float p = (float)g_hist[bin] / (float)Nn;
        e += p * logf(p + 1e-10f);
    }
    red[tid] = e;
    __syncthreads();
    for (int s = 128; s > 0; s >>= 1) {
        if (tid < s) red[tid] += red[tid + s];
        __syncthreads();
    }
    if (tid == 0 && extras) {
        out[Q_ELEMS + 0] = mse;
        out[Q_ELEMS + 1] = mse;
        out[Q_ELEMS + 2] = red[0];
    }
}

// ---------------------------------------------------------------------------
extern "C" void kernel_launch(void* const* d_in, const int* in_sizes, int n_in,
                              void* d_out, int out_size) {
    const float* x = (const float*)d_in[0];   // [32,256,32,32]
    const float* E = (const float*)d_in[1];   // [256,2048]
    float* out = (float*)d_out;
    const int extras = (out_size >= FULL_OUT) ? 1 : 0;

    k_invnorm<<<Kk / 256, 256>>>(E);
    k_prepe<<<dim3(Kk / 64, Dd / 64), 256>>>(E);

    cudaFuncSetAttribute(k_mma_argmax,
                         cudaFuncAttributeMaxDynamicSharedMemorySize, SM_TOT);
    k_mma_argmax<<<Nn / 64, 256, SM_TOT>>>(x);

    k_rescue<<<1024, 256>>>(x);
    k_pick<<<4, 256>>>();
    k_gather<<<dim3(Nn / 1024, 8), 256>>>(x, E, out, extras);
    k_final<<<1, 256>>>(out, extras);
}